// round 1
// baseline (speedup 1.0000x reference)
#include <cuda_runtime.h>
#include <cstddef>

// f = H @ x + damp * x, per molecule. hess: [M*96, 96] f32 row-major,
// ns: [M*96] f32 (flattened [N_tot,3]), out: [M*96] f32.
#define D 96
#define DD (D * D)

// 0.1 * 627.5094740631 / 0.529177210903^2
__device__ __constant__ float kDampF = (float)(0.1 * 627.5094740631 /
                                               (0.529177210903 * 0.529177210903));

__global__ __launch_bounds__(D, 6)
void force_agg_kernel(const float* __restrict__ ns,
                      const float* __restrict__ hess,
                      float* __restrict__ out) {
    __shared__ float Hs[DD];   // 36864 B, row-major, no pad (rotation avoids conflicts)
    __shared__ float xs[D];

    const int m = blockIdx.x;
    const int t = threadIdx.x;          // 0..95

    // load x (coalesced, 96 consecutive floats)
    xs[t] = ns[(size_t)m * D + t];

    // stage H block: 9216 floats = 2304 float4, 96 threads -> 24 iters, fully coalesced
    const float4* __restrict__ Hg = reinterpret_cast<const float4*>(hess + (size_t)m * DD);
    float4* Hs4 = reinterpret_cast<float4*>(Hs);
    #pragma unroll
    for (int k = 0; k < DD / 4 / D; ++k) {
        Hs4[k * D + t] = Hg[k * D + t];
    }
    __syncthreads();

    // row-i dot product with rotated column start (bank-conflict-free:
    // 96 % 32 == 0 so bank = (t + it) % 32 covers all banks per warp)
    float acc = kDampF * xs[t];
    const float* __restrict__ Hrow = &Hs[t * D];
    int j = t;
    #pragma unroll 8
    for (int it = 0; it < D; ++it) {
        acc = fmaf(Hrow[j], xs[j], acc);
        ++j;
        if (j == D) j = 0;
    }

    // coalesced store
    out[(size_t)m * D + t] = acc;
}

extern "C" void kernel_launch(void* const* d_in, const int* in_sizes, int n_in,
                              void* d_out, int out_size) {
    const float* ns   = (const float*)d_in[0];   // [N_tot, 3] -> flat [M*96]
    const float* hess = (const float*)d_in[1];   // [M*96, 96]
    // d_in[2] = idx_m (unused: uniform sorted), d_in[3] = n_atoms (unused)
    float* out = (float*)d_out;

    const int M = in_sizes[1] / DD;              // 8192
    force_agg_kernel<<<M, D>>>(ns, hess, out);
}

// round 2
// speedup vs baseline: 1.1836x; 1.1836x over previous
#include <cuda_runtime.h>
#include <cstdint>
#include <cstddef>

// f = H @ x + damp * x per molecule.
// hess: [M*96, 96] f32 row-major, ns: flat [M*96] f32, out: flat [M*96] f32.
#define D 96
#define DD (D * D)
#define H_BYTES (DD * 4)       // 36864
#define X_BYTES (D * 4)        // 384
#define NBLOCKS 456            // 152 SMs * 3 CTAs/SM (GB300)

// dynamic smem layout:
//   [0,            2*H_BYTES)              : H stages (2 x 36864)
//   [2*H_BYTES,    2*H_BYTES + 2*X_BYTES)  : x stages (2 x 384)
//   [...,          +16)                    : 2 mbarriers (8B each)
#define SMEM_X_OFF   (2 * H_BYTES)
#define SMEM_MBAR_OFF (2 * H_BYTES + 2 * X_BYTES)
#define SMEM_TOTAL   (SMEM_MBAR_OFF + 16)

__device__ __constant__ float kDampF = (float)(0.1 * 627.5094740631 /
                                               (0.529177210903 * 0.529177210903));

__device__ __forceinline__ uint32_t s2u(const void* p) {
    uint32_t a;
    asm("{ .reg .u64 t; cvta.to.shared.u64 t, %1; cvt.u32.u64 %0, t; }"
        : "=r"(a) : "l"(p));
    return a;
}

__device__ __forceinline__ void mbar_init(uint32_t mbar, uint32_t count) {
    asm volatile("mbarrier.init.shared.b64 [%0], %1;" :: "r"(mbar), "r"(count) : "memory");
}

__device__ __forceinline__ void mbar_expect_tx(uint32_t mbar, uint32_t bytes) {
    asm volatile("mbarrier.arrive.expect_tx.shared.b64 _, [%0], %1;"
                 :: "r"(mbar), "r"(bytes) : "memory");
}

__device__ __forceinline__ void mbar_wait(uint32_t mbar, uint32_t parity) {
    asm volatile(
        "{\n\t"
        ".reg .pred P;\n\t"
        "WAIT_%=:\n\t"
        "mbarrier.try_wait.parity.shared.b64 P, [%0], %1;\n\t"
        "@!P bra WAIT_%=;\n\t"
        "}"
        :: "r"(mbar), "r"(parity) : "memory");
}

__device__ __forceinline__ void bulk_g2s(uint32_t dst_smem, const void* src_gmem,
                                         uint32_t bytes, uint32_t mbar) {
    asm volatile(
        "cp.async.bulk.shared::cluster.global.mbarrier::complete_tx::bytes "
        "[%0], [%1], %2, [%3];"
        :: "r"(dst_smem), "l"(src_gmem), "r"(bytes), "r"(mbar) : "memory");
}

extern __shared__ char smem_raw[];

__global__ void __launch_bounds__(D, 3)
force_agg_kernel(const float* __restrict__ ns,
                 const float* __restrict__ hess,
                 float* __restrict__ out, int M) {
    float* Hs = reinterpret_cast<float*>(smem_raw);                 // [2][DD]
    float* xs = reinterpret_cast<float*>(smem_raw + SMEM_X_OFF);    // [2][D]
    uint32_t mbar0 = s2u(smem_raw + SMEM_MBAR_OFF);
    uint32_t mbar1 = mbar0 + 8;

    const int t = threadIdx.x;     // 0..95
    const int b = blockIdx.x;

    if (t == 0) {
        mbar_init(mbar0, 1);
        mbar_init(mbar1, 1);
    }
    __syncthreads();

    // molecules handled by this block: b, b+grid, b+2*grid, ...
    const int stride = gridDim.x;
    const int cnt = (b < M) ? (M - b + stride - 1) / stride : 0;
    if (cnt == 0) return;

    const uint32_t Hs_u = s2u(Hs);
    const uint32_t xs_u = s2u(xs);

    // prologue: issue stage 0 for k=0
    if (t == 0) {
        int m0 = b;
        mbar_expect_tx(mbar0, H_BYTES + X_BYTES);
        bulk_g2s(Hs_u, hess + (size_t)m0 * DD, H_BYTES, mbar0);
        bulk_g2s(xs_u, ns + (size_t)m0 * D, X_BYTES, mbar0);
    }

    uint32_t phase0 = 0, phase1 = 0;

    for (int k = 0; k < cnt; ++k) {
        const int s = k & 1;
        const uint32_t mbar_s = s ? mbar1 : mbar0;

        // prefetch k+1 into stage s^1 (that stage's consumers finished at
        // the __syncthreads ending iteration k-1)
        if (t == 0 && (k + 1) < cnt) {
            const int s2 = s ^ 1;
            const int m2 = b + (k + 1) * stride;
            const uint32_t mbar_n = s2 ? mbar1 : mbar0;
            mbar_expect_tx(mbar_n, H_BYTES + X_BYTES);
            bulk_g2s(Hs_u + (uint32_t)s2 * H_BYTES,
                     hess + (size_t)m2 * DD, H_BYTES, mbar_n);
            bulk_g2s(xs_u + 2u * H_BYTES - SMEM_X_OFF + (uint32_t)s2 * X_BYTES - (2u * H_BYTES - SMEM_X_OFF),
                     ns + (size_t)m2 * D, X_BYTES, mbar_n);
        }

        // wait for stage s data
        if (s) { mbar_wait(mbar1, phase1); phase1 ^= 1; }
        else   { mbar_wait(mbar0, phase0); phase0 ^= 1; }

        // compute: rotated-column dot product (bank-conflict-free since 96%32==0)
        const float* __restrict__ Hrow = Hs + (size_t)s * DD + (size_t)t * D;
        const float* __restrict__ xv   = xs + s * D;
        float acc = kDampF * xv[t];
        int j = t;
        #pragma unroll 8
        for (int it = 0; it < D; ++it) {
            acc = fmaf(Hrow[j], xv[j], acc);
            ++j;
            if (j == D) j = 0;
        }

        const int mk = b + k * stride;
        out[(size_t)mk * D + t] = acc;

        // all smem reads of stage s done before it is refilled at iter k+1's prefetch
        __syncthreads();
    }
}

extern "C" void kernel_launch(void* const* d_in, const int* in_sizes, int n_in,
                              void* d_out, int out_size) {
    const float* ns   = (const float*)d_in[0];   // [N_tot,3] -> flat [M*96]
    const float* hess = (const float*)d_in[1];   // [M*96, 96]
    float* out = (float*)d_out;

    const int M = in_sizes[1] / DD;              // 8192

    cudaFuncSetAttribute(force_agg_kernel,
                         cudaFuncAttributeMaxDynamicSharedMemorySize, SMEM_TOTAL);
    force_agg_kernel<<<NBLOCKS, D, SMEM_TOTAL>>>(ns, hess, out, M);
}

// round 3
// speedup vs baseline: 1.2822x; 1.0833x over previous
#include <cuda_runtime.h>
#include <cstdint>
#include <cstddef>

// f = H @ x + damp * x per molecule.
// hess: [M*96, 96] f32 row-major, ns: flat [M*96] f32, out: flat [M*96] f32.
#define D 96
#define D4 24                  // D/4 vec4 columns
#define DD (D * D)
#define H_BYTES (DD * 4)       // 36864
#define X_BYTES (D * 4)        // 384
#define NBLOCKS 456            // 152 SMs * 3 CTAs/SM (GB300)

// dynamic smem layout:
//   [0,            2*H_BYTES)              : H stages (2 x 36864)
//   [2*H_BYTES,    2*H_BYTES + 2*X_BYTES)  : x stages (2 x 384)
//   [...,          +16)                    : 2 mbarriers (8B each)
#define SMEM_X_OFF    (2 * H_BYTES)
#define SMEM_MBAR_OFF (2 * H_BYTES + 2 * X_BYTES)
#define SMEM_TOTAL    (SMEM_MBAR_OFF + 16)

__device__ __constant__ float kDampF = (float)(0.1 * 627.5094740631 /
                                               (0.529177210903 * 0.529177210903));

__device__ __forceinline__ uint32_t s2u(const void* p) {
    uint32_t a;
    asm("{ .reg .u64 t; cvta.to.shared.u64 t, %1; cvt.u32.u64 %0, t; }"
        : "=r"(a) : "l"(p));
    return a;
}

__device__ __forceinline__ void mbar_init(uint32_t mbar, uint32_t count) {
    asm volatile("mbarrier.init.shared.b64 [%0], %1;" :: "r"(mbar), "r"(count) : "memory");
}

__device__ __forceinline__ void mbar_expect_tx(uint32_t mbar, uint32_t bytes) {
    asm volatile("mbarrier.arrive.expect_tx.shared.b64 _, [%0], %1;"
                 :: "r"(mbar), "r"(bytes) : "memory");
}

__device__ __forceinline__ void mbar_wait(uint32_t mbar, uint32_t parity) {
    asm volatile(
        "{\n\t"
        ".reg .pred P;\n\t"
        "WAIT_%=:\n\t"
        "mbarrier.try_wait.parity.shared.b64 P, [%0], %1;\n\t"
        "@!P bra WAIT_%=;\n\t"
        "}"
        :: "r"(mbar), "r"(parity) : "memory");
}

__device__ __forceinline__ void bulk_g2s(uint32_t dst_smem, const void* src_gmem,
                                         uint32_t bytes, uint32_t mbar) {
    asm volatile(
        "cp.async.bulk.shared::cluster.global.mbarrier::complete_tx::bytes "
        "[%0], [%1], %2, [%3];"
        :: "r"(dst_smem), "l"(src_gmem), "r"(bytes), "r"(mbar) : "memory");
}

extern __shared__ char smem_raw[];

__global__ void __launch_bounds__(D, 3)
force_agg_kernel(const float* __restrict__ ns,
                 const float* __restrict__ hess,
                 float* __restrict__ out, int M) {
    float* Hs = reinterpret_cast<float*>(smem_raw);                 // [2][DD]
    float* xs = reinterpret_cast<float*>(smem_raw + SMEM_X_OFF);    // [2][D]
    uint32_t mbar0 = s2u(smem_raw + SMEM_MBAR_OFF);
    uint32_t mbar1 = mbar0 + 8;

    const int t = threadIdx.x;     // 0..95
    const int b = blockIdx.x;

    if (t == 0) {
        mbar_init(mbar0, 1);
        mbar_init(mbar1, 1);
    }
    __syncthreads();

    const int stride = gridDim.x;
    const int cnt = (b < M) ? (M - b + stride - 1) / stride : 0;
    if (cnt == 0) return;

    const uint32_t Hs_u = s2u(Hs);
    const uint32_t xs_u = s2u(xs);

    // prologue: stage 0 for k=0
    if (t == 0) {
        mbar_expect_tx(mbar0, H_BYTES + X_BYTES);
        bulk_g2s(Hs_u, hess + (size_t)b * DD, H_BYTES, mbar0);
        bulk_g2s(xs_u, ns + (size_t)b * D, X_BYTES, mbar0);
    }

    uint32_t phase0 = 0, phase1 = 0;
    const int c0 = t % D4;         // rotated vec4-column start (conflict-free)

    for (int k = 0; k < cnt; ++k) {
        const int s = k & 1;

        // prefetch k+1 into stage s^1 (freed by the sync at the end of iter k-1)
        if (t == 0 && (k + 1) < cnt) {
            const int s2 = s ^ 1;
            const int m2 = b + (k + 1) * stride;
            const uint32_t mbar_n = s2 ? mbar1 : mbar0;
            mbar_expect_tx(mbar_n, H_BYTES + X_BYTES);
            bulk_g2s(Hs_u + (uint32_t)s2 * H_BYTES,
                     hess + (size_t)m2 * DD, H_BYTES, mbar_n);
            bulk_g2s(xs_u + (uint32_t)s2 * X_BYTES,
                     ns + (size_t)m2 * D, X_BYTES, mbar_n);
        }

        // wait for stage s
        if (s) { mbar_wait(mbar1, phase1); phase1 ^= 1; }
        else   { mbar_wait(mbar0, phase0); phase0 ^= 1; }

        // vectorized dot product: LDS.128 on H row and x, rotated start.
        // 16B-group = ((t*24 + c) mod 8) = (c mod 8): distinct per 8-lane phase.
        const float4* __restrict__ Hrow4 =
            reinterpret_cast<const float4*>(Hs + (size_t)s * DD + (size_t)t * D);
        const float4* __restrict__ xv4 =
            reinterpret_cast<const float4*>(xs + s * D);

        float a0 = 0.f, a1 = 0.f, a2 = 0.f, a3 = 0.f;
        int c = c0;
        #pragma unroll
        for (int it = 0; it < D4; ++it) {
            float4 h = Hrow4[c];
            float4 xv = xv4[c];
            a0 = fmaf(h.x, xv.x, a0);
            a1 = fmaf(h.y, xv.y, a1);
            a2 = fmaf(h.z, xv.z, a2);
            a3 = fmaf(h.w, xv.w, a3);
            ++c;
            if (c == D4) c = 0;
        }
        const float x_t = (xs + s * D)[t];
        const float acc = fmaf(kDampF, x_t, (a0 + a1) + (a2 + a3));

        const int mk = b + k * stride;
        out[(size_t)mk * D + t] = acc;

        // stage s fully consumed before iter k+1 refills it
        __syncthreads();
    }
}

extern "C" void kernel_launch(void* const* d_in, const int* in_sizes, int n_in,
                              void* d_out, int out_size) {
    const float* ns   = (const float*)d_in[0];   // [N_tot,3] -> flat [M*96]
    const float* hess = (const float*)d_in[1];   // [M*96, 96]
    float* out = (float*)d_out;

    const int M = in_sizes[1] / DD;              // 8192

    cudaFuncSetAttribute(force_agg_kernel,
                         cudaFuncAttributeMaxDynamicSharedMemorySize, SMEM_TOTAL);
    force_agg_kernel<<<NBLOCKS, D, SMEM_TOTAL>>>(ns, hess, out, M);
}